// round 1
// baseline (speedup 1.0000x reference)
#include <cuda_runtime.h>
#include <math.h>

#define BATCH 2
#define SEQ   4096
#define DMODEL 1024

// Scratch (alloc-free rule: __device__ globals)
__device__ float g_Q[BATCH * SEQ * DMODEL];
__device__ float g_K[BATCH * SEQ * DMODEL];
__device__ float g_V[BATCH * SEQ * DMODEL];
__device__ float g_O[BATCH * SEQ * DMODEL];
__device__ float g_A[(size_t)BATCH * SEQ * SEQ];   // 134 MB
__device__ float g_decay[SEQ];

// ---------------------------------------------------------------------------
// decay table: gamma^d, gamma = 255/256 exactly. Double precision init.
// ---------------------------------------------------------------------------
__global__ void init_decay_kernel() {
    int i = blockIdx.x * blockDim.x + threadIdx.x;
    if (i < SEQ) g_decay[i] = (float)exp((double)i * log(255.0 / 256.0));
}

// ---------------------------------------------------------------------------
// 128x128x8 fp32 SGEMM, 256 threads, 8x8 per-thread microtile.
// TRB: B operand is N x K row-major (i.e. C = A * B^T).
// DECAY: multiply C[r][c] by gamma^(c-r) for c>=r else 0 (A = QK^T epilogue).
// Dims assumed multiples of 128 (rows/cols) and 8 (K) — true for this problem.
// ---------------------------------------------------------------------------
template<bool TRB, bool DECAY>
__global__ void __launch_bounds__(256) sgemm128(
    const float* __restrict__ Ag, const float* __restrict__ Bg,
    float* __restrict__ Cg,
    int Kdim, int lda, int ldb, int ldc,
    size_t sA, size_t sB, size_t sC)
{
    __shared__ __align__(16) float As[8][132];
    __shared__ __align__(16) float Bs[8][132];

    const float* Ab = Ag + (size_t)blockIdx.z * sA;
    const float* Bb = Bg + (size_t)blockIdx.z * sB;
    float*       Cb = Cg + (size_t)blockIdx.z * sC;

    const int tid  = threadIdx.x;
    const int tx   = tid & 15;
    const int ty   = tid >> 4;
    const int row0 = blockIdx.y * 128;
    const int col0 = blockIdx.x * 128;

    const int lrow = tid >> 1;          // 0..127
    const int lc4  = (tid & 1) * 4;     // 0 or 4
    const int bro  = tid >> 5;          // 0..7   (NN B load)
    const int bco  = (tid & 31) * 4;    // 0..124

    float acc[8][8];
#pragma unroll
    for (int i = 0; i < 8; i++)
#pragma unroll
        for (int j = 0; j < 8; j++) acc[i][j] = 0.0f;

    float ra[8], rb[8];

    for (int k0 = 0; k0 < Kdim; k0 += 8) {
        // --- load A tile (128 x 8), store transposed As[k][row] ---
        {
            float4 av = *(const float4*)(Ab + (size_t)(row0 + lrow) * lda + k0 + lc4);
            As[lc4 + 0][lrow] = av.x;
            As[lc4 + 1][lrow] = av.y;
            As[lc4 + 2][lrow] = av.z;
            As[lc4 + 3][lrow] = av.w;
        }
        // --- load B tile into Bs[k][col] ---
        if (TRB) {
            // B is N x K: Bs[k][n] = B[n, k]
            float4 bv = *(const float4*)(Bb + (size_t)(col0 + lrow) * ldb + k0 + lc4);
            Bs[lc4 + 0][lrow] = bv.x;
            Bs[lc4 + 1][lrow] = bv.y;
            Bs[lc4 + 2][lrow] = bv.z;
            Bs[lc4 + 3][lrow] = bv.w;
        } else {
            // B is K x N
            float4 bv = *(const float4*)(Bb + (size_t)(k0 + bro) * ldb + col0 + bco);
            *(float4*)&Bs[bro][bco] = bv;
        }
        __syncthreads();

#pragma unroll
        for (int k = 0; k < 8; k++) {
#pragma unroll
            for (int i = 0; i < 8; i++) ra[i] = As[k][ty * 8 + i];
#pragma unroll
            for (int j = 0; j < 8; j++) rb[j] = Bs[k][tx * 8 + j];
#pragma unroll
            for (int i = 0; i < 8; i++)
#pragma unroll
                for (int j = 0; j < 8; j++)
                    acc[i][j] = fmaf(ra[i], rb[j], acc[i][j]);
        }
        __syncthreads();
    }

    // --- epilogue ---
#pragma unroll
    for (int i = 0; i < 8; i++) {
        int r = row0 + ty * 8 + i;
        float* crow = Cb + (size_t)r * ldc + col0 + tx * 8;
#pragma unroll
        for (int jj = 0; jj < 2; jj++) {
            float4 v;
            v.x = acc[i][jj * 4 + 0];
            v.y = acc[i][jj * 4 + 1];
            v.z = acc[i][jj * 4 + 2];
            v.w = acc[i][jj * 4 + 3];
            if (DECAY) {
                int cbase = col0 + tx * 8 + jj * 4;
                int d0 = cbase + 0 - r;
                int d1 = cbase + 1 - r;
                int d2 = cbase + 2 - r;
                int d3 = cbase + 3 - r;
                v.x = (d0 >= 0) ? v.x * g_decay[d0] : 0.0f;
                v.y = (d1 >= 0) ? v.y * g_decay[d1] : 0.0f;
                v.z = (d2 >= 0) ? v.z * g_decay[d2] : 0.0f;
                v.w = (d3 >= 0) ? v.w * g_decay[d3] : 0.0f;
            }
            *(float4*)(crow + jj * 4) = v;
        }
    }
}

// ---------------------------------------------------------------------------
// rope (first 64 channels) + silu, in-place, one thread per channel PAIR so
// the rotate has no read/write race. Double-precision trig: t up to 4095 rad,
// fast-math sinf/cosf range reduction is not accurate enough.
// ---------------------------------------------------------------------------
template<bool DO_ROPE>
__global__ void act_kernel(float* __restrict__ buf)
{
    int p = blockIdx.x * blockDim.x + threadIdx.x;   // pair index
    if (p >= BATCH * SEQ * (DMODEL / 2)) return;
    float2 v = ((float2*)buf)[p];
    float y0 = v.x, y1 = v.y;
    if (DO_ROPE) {
        int cp = p & (DMODEL / 2 - 1);               // pair within row
        if (cp < 32) {                               // ROPE_DIM/2 = 32 pairs
            int t = (p >> 9) & (SEQ - 1);            // row % SEQ
            // inv_freq = 10000^(-cp/32); ln(10000)/32 = 0.28782313662425574
            double fr = (double)t * exp((double)cp * -0.28782313662425574);
            float cs = (float)cos(fr);
            float sn = (float)sin(fr);
            float a = v.x, b = v.y;
            y0 = a * cs - b * sn;
            y1 = b * cs + a * sn;
        }
    }
    y0 = y0 / (1.0f + expf(-y0));
    y1 = y1 / (1.0f + expf(-y1));
    ((float2*)buf)[p] = make_float2(y0, y1);
}

// ---------------------------------------------------------------------------
// GroupNorm: 32 groups of 32 channels per row. One warp per group,
// two-pass (mean then centered var) for numerical safety.
// ---------------------------------------------------------------------------
__global__ void groupnorm_kernel(const float* __restrict__ in,
                                 const float* __restrict__ w,
                                 const float* __restrict__ bvec,
                                 float* __restrict__ out)
{
    int row  = blockIdx.x;
    int warp = threadIdx.x >> 5;
    int lane = threadIdx.x & 31;
    const float* r = in  + (size_t)row * DMODEL;
    float*       o = out + (size_t)row * DMODEL;
    for (int g = warp; g < 32; g += 8) {
        int ch = g * 32 + lane;
        float v = r[ch];
        float s = v;
#pragma unroll
        for (int off = 16; off; off >>= 1) s += __shfl_xor_sync(0xffffffffu, s, off);
        float mu = s * (1.0f / 32.0f);
        float dv = v - mu;
        float s2 = dv * dv;
#pragma unroll
        for (int off = 16; off; off >>= 1) s2 += __shfl_xor_sync(0xffffffffu, s2, off);
        float var = s2 * (1.0f / 32.0f);
        float xn = dv * rsqrtf(var + 1e-6f);
        o[ch] = xn * w[ch] + bvec[ch];
    }
}

// ---------------------------------------------------------------------------
extern "C" void kernel_launch(void* const* d_in, const int* in_sizes, int n_in,
                              void* d_out, int out_size)
{
    (void)in_sizes; (void)n_in; (void)out_size;
    const float* X  = (const float*)d_in[0];
    const float* WQ = (const float*)d_in[1];
    const float* WK = (const float*)d_in[2];
    const float* WV = (const float*)d_in[3];
    const float* gw = (const float*)d_in[4];
    const float* gb = (const float*)d_in[5];
    float* out = (float*)d_out;

    float *pQ, *pK, *pV, *pO, *pA;
    cudaGetSymbolAddress((void**)&pQ, g_Q);
    cudaGetSymbolAddress((void**)&pK, g_K);
    cudaGetSymbolAddress((void**)&pV, g_V);
    cudaGetSymbolAddress((void**)&pO, g_O);
    cudaGetSymbolAddress((void**)&pA, g_A);

    init_decay_kernel<<<(SEQ + 255) / 256, 256>>>();

    // Projections: (B*T, 1024) @ (1024, 1024)
    dim3 gProj(DMODEL / 128, (BATCH * SEQ) / 128, 1);
    sgemm128<false, false><<<gProj, 256>>>(X, WQ, pQ, DMODEL, DMODEL, DMODEL, DMODEL, 0, 0, 0);
    sgemm128<false, false><<<gProj, 256>>>(X, WK, pK, DMODEL, DMODEL, DMODEL, DMODEL, 0, 0, 0);
    sgemm128<false, false><<<gProj, 256>>>(X, WV, pV, DMODEL, DMODEL, DMODEL, DMODEL, 0, 0, 0);

    // rope + silu (Q, K), silu (V)
    int pairs = BATCH * SEQ * (DMODEL / 2);
    int ablocks = (pairs + 255) / 256;
    act_kernel<true ><<<ablocks, 256>>>(pQ);
    act_kernel<true ><<<ablocks, 256>>>(pK);
    act_kernel<false><<<ablocks, 256>>>(pV);

    // A = Q K^T with decay epilogue (per batch)
    dim3 gA(SEQ / 128, SEQ / 128, BATCH);
    sgemm128<true, true><<<gA, 256>>>(pQ, pK, pA, DMODEL, DMODEL, DMODEL, SEQ,
                                      (size_t)SEQ * DMODEL, (size_t)SEQ * DMODEL,
                                      (size_t)SEQ * SEQ);

    // O = A V (per batch)
    dim3 gO(DMODEL / 128, SEQ / 128, BATCH);
    sgemm128<false, false><<<gO, 256>>>(pA, pV, pO, SEQ, SEQ, DMODEL, DMODEL,
                                        (size_t)SEQ * SEQ, (size_t)SEQ * DMODEL,
                                        (size_t)SEQ * DMODEL);

    // GroupNorm -> d_out
    groupnorm_kernel<<<BATCH * SEQ, 256>>>(pO, gw, gb, out);
}

// round 2
// speedup vs baseline: 2.4666x; 2.4666x over previous
#include <cuda_runtime.h>
#include <math.h>

#define BATCH 2
#define SEQ   4096
#define DMODEL 1024

// Scratch (alloc-free rule: __device__ globals)
__device__ float g_Q[BATCH * SEQ * DMODEL];
__device__ float g_K[BATCH * SEQ * DMODEL];
__device__ float g_V[BATCH * SEQ * DMODEL];
__device__ float g_O[BATCH * SEQ * DMODEL];
__device__ float g_A[(size_t)BATCH * SEQ * SEQ];   // 134 MB
__device__ float g_decay[SEQ];

// ---------------------------------------------------------------------------
__global__ void init_decay_kernel() {
    int i = blockIdx.x * blockDim.x + threadIdx.x;
    if (i < SEQ) g_decay[i] = (float)exp((double)i * log(255.0 / 256.0));
}

// fp32 -> tf32 with round-to-nearest (truncation would bias products low)
__device__ __forceinline__ unsigned f2tf(float f) {
    unsigned o;
    asm("cvt.rna.tf32.f32 %0, %1;" : "=r"(o) : "f"(f));
    return o;
}

__device__ __forceinline__ void mma8(float* c, const unsigned* a, const unsigned* b) {
    asm volatile(
        "mma.sync.aligned.m16n8k8.row.col.f32.tf32.tf32.f32 "
        "{%0,%1,%2,%3}, {%4,%5,%6,%7}, {%8,%9}, {%0,%1,%2,%3};"
        : "+f"(c[0]), "+f"(c[1]), "+f"(c[2]), "+f"(c[3])
        : "r"(a[0]), "r"(a[1]), "r"(a[2]), "r"(a[3]), "r"(b[0]), "r"(b[1]));
}

// ---------------------------------------------------------------------------
// tf32 tensor-core GEMM. Block tile 128x128, K-tile 32, 256 threads (8 warps).
// Warp tile 64x32 (warps in 2x4 grid), built from m16n8k8 MMAs (4 m-tiles x
// 4 n-tiles, 64 accum regs/thread).
// TRB:   C = A * B^T  (B given N x K row-major)
// DECAY: C[r][c] *= gamma^(c-r) for c>=r else 0  (QK^T epilogue)
// All dims multiples of 128 (M,N) and 32 (K).
// Smem pad 136 words: 136%32==8, so the fragment read pattern q*8+g covers
// all 32 banks -> conflict-free compute loads; 136%4==0 keeps 16B alignment.
// ---------------------------------------------------------------------------
#define PAD 136
template<bool TRB, bool DECAY>
__global__ void __launch_bounds__(256) tf32gemm(
    const float* __restrict__ Ag, const float* __restrict__ Bg,
    float* __restrict__ Cg,
    int Kdim, int lda, int ldb, int ldc,
    size_t sA, size_t sB, size_t sC)
{
    __shared__ unsigned As[32][PAD];   // As[k][m]
    __shared__ unsigned Bs[32][PAD];   // Bs[k][n]

    const float* Ab = Ag + (size_t)blockIdx.z * sA;
    const float* Bb = Bg + (size_t)blockIdx.z * sB;
    float*       Cb = Cg + (size_t)blockIdx.z * sC;

    const int tid  = threadIdx.x;
    const int lane = tid & 31;
    const int wid  = tid >> 5;
    const int wm   = (wid & 1) * 64;    // warp row offset in tile
    const int wn   = (wid >> 1) * 32;   // warp col offset in tile
    const int g    = lane >> 2;         // 0..7
    const int q    = lane & 3;          // 0..3
    const int row0 = blockIdx.y * 128;
    const int col0 = blockIdx.x * 128;

    float acc[4][4][4];
#pragma unroll
    for (int mt = 0; mt < 4; mt++)
#pragma unroll
        for (int nt = 0; nt < 4; nt++)
#pragma unroll
            for (int i = 0; i < 4; i++) acc[mt][nt][i] = 0.0f;

    // fill-time indices
    const int fm = tid >> 1;            // 0..127 (row for A / TRB-B fill)
    const int fk = (tid & 1) * 4;       // 0 or 4
    const int bk = tid >> 3;            // 0..31  (k row for NN-B fill)
    const int bc = (tid & 7) * 4;       // 0..28

    for (int k0 = 0; k0 < Kdim; k0 += 32) {
        // ---- stage A tile: As[k][m] = tf32(A[row0+m][k0+k]) ----
        {
            const float* arow = Ab + (size_t)(row0 + fm) * lda + k0 + fk;
#pragma unroll
            for (int p = 0; p < 4; p++) {
                float4 v = *(const float4*)(arow + p * 8);
                int kk = p * 8 + fk;
                As[kk + 0][fm] = f2tf(v.x);
                As[kk + 1][fm] = f2tf(v.y);
                As[kk + 2][fm] = f2tf(v.z);
                As[kk + 3][fm] = f2tf(v.w);
            }
        }
        // ---- stage B tile: Bs[k][n] = tf32(B^T logical) ----
        if (TRB) {
            const float* brow = Bb + (size_t)(col0 + fm) * ldb + k0 + fk;
#pragma unroll
            for (int p = 0; p < 4; p++) {
                float4 v = *(const float4*)(brow + p * 8);
                int kk = p * 8 + fk;
                Bs[kk + 0][fm] = f2tf(v.x);
                Bs[kk + 1][fm] = f2tf(v.y);
                Bs[kk + 2][fm] = f2tf(v.z);
                Bs[kk + 3][fm] = f2tf(v.w);
            }
        } else {
            const float* brow = Bb + (size_t)(k0 + bk) * ldb + col0 + bc;
#pragma unroll
            for (int p = 0; p < 4; p++) {
                float4 v = *(const float4*)(brow + p * 32);
                uint4 t;
                t.x = f2tf(v.x); t.y = f2tf(v.y);
                t.z = f2tf(v.z); t.w = f2tf(v.w);
                *(uint4*)&Bs[bk][p * 32 + bc] = t;
            }
        }
        __syncthreads();

        // ---- compute: 4 k-steps of 8 ----
#pragma unroll
        for (int ks = 0; ks < 4; ks++) {
            const int kb = ks * 8;
            unsigned a[4][4], b[4][2];
#pragma unroll
            for (int mt = 0; mt < 4; mt++) {
                int m = wm + mt * 16 + g;
                a[mt][0] = As[kb + q][m];
                a[mt][1] = As[kb + q][m + 8];
                a[mt][2] = As[kb + q + 4][m];
                a[mt][3] = As[kb + q + 4][m + 8];
            }
#pragma unroll
            for (int nt = 0; nt < 4; nt++) {
                int n = wn + nt * 8 + g;
                b[nt][0] = Bs[kb + q][n];
                b[nt][1] = Bs[kb + q + 4][n];
            }
#pragma unroll
            for (int mt = 0; mt < 4; mt++)
#pragma unroll
                for (int nt = 0; nt < 4; nt++)
                    mma8(acc[mt][nt], a[mt], b[nt]);
        }
        __syncthreads();
    }

    // ---- epilogue ----
#pragma unroll
    for (int mt = 0; mt < 4; mt++) {
#pragma unroll
        for (int nt = 0; nt < 4; nt++) {
            int r = row0 + wm + mt * 16 + g;
            int c = col0 + wn + nt * 8 + 2 * q;
            float v0 = acc[mt][nt][0], v1 = acc[mt][nt][1];
            float v2 = acc[mt][nt][2], v3 = acc[mt][nt][3];
            if (DECAY) {
                int d0 = c - r, d1 = c + 1 - r;
                int d2 = c - (r + 8), d3 = c + 1 - (r + 8);
                v0 = (d0 >= 0) ? v0 * g_decay[d0] : 0.0f;
                v1 = (d1 >= 0) ? v1 * g_decay[d1] : 0.0f;
                v2 = (d2 >= 0) ? v2 * g_decay[d2] : 0.0f;
                v3 = (d3 >= 0) ? v3 * g_decay[d3] : 0.0f;
            }
            *(float2*)(Cb + (size_t)r * ldc + c)       = make_float2(v0, v1);
            *(float2*)(Cb + (size_t)(r + 8) * ldc + c) = make_float2(v2, v3);
        }
    }
}

// ---------------------------------------------------------------------------
// rope (first 64 channels) + silu. Double-precision trig (t up to 4095 rad).
// ---------------------------------------------------------------------------
template<bool DO_ROPE>
__global__ void act_kernel(float* __restrict__ buf)
{
    int p = blockIdx.x * blockDim.x + threadIdx.x;   // pair index
    if (p >= BATCH * SEQ * (DMODEL / 2)) return;
    float2 v = ((float2*)buf)[p];
    float y0 = v.x, y1 = v.y;
    if (DO_ROPE) {
        int cp = p & (DMODEL / 2 - 1);
        if (cp < 32) {
            int t = (p >> 9) & (SEQ - 1);
            double fr = (double)t * exp((double)cp * -0.28782313662425574);
            float cs = (float)cos(fr);
            float sn = (float)sin(fr);
            float a = v.x, b = v.y;
            y0 = a * cs - b * sn;
            y1 = b * cs + a * sn;
        }
    }
    y0 = y0 / (1.0f + expf(-y0));
    y1 = y1 / (1.0f + expf(-y1));
    ((float2*)buf)[p] = make_float2(y0, y1);
}

// ---------------------------------------------------------------------------
__global__ void groupnorm_kernel(const float* __restrict__ in,
                                 const float* __restrict__ w,
                                 const float* __restrict__ bvec,
                                 float* __restrict__ out)
{
    int row  = blockIdx.x;
    int warp = threadIdx.x >> 5;
    int lane = threadIdx.x & 31;
    const float* r = in  + (size_t)row * DMODEL;
    float*       o = out + (size_t)row * DMODEL;
    for (int g = warp; g < 32; g += 8) {
        int ch = g * 32 + lane;
        float v = r[ch];
        float s = v;
#pragma unroll
        for (int off = 16; off; off >>= 1) s += __shfl_xor_sync(0xffffffffu, s, off);
        float mu = s * (1.0f / 32.0f);
        float dv = v - mu;
        float s2 = dv * dv;
#pragma unroll
        for (int off = 16; off; off >>= 1) s2 += __shfl_xor_sync(0xffffffffu, s2, off);
        float var = s2 * (1.0f / 32.0f);
        float xn = dv * rsqrtf(var + 1e-6f);
        o[ch] = xn * w[ch] + bvec[ch];
    }
}

// ---------------------------------------------------------------------------
extern "C" void kernel_launch(void* const* d_in, const int* in_sizes, int n_in,
                              void* d_out, int out_size)
{
    (void)in_sizes; (void)n_in; (void)out_size;
    const float* X  = (const float*)d_in[0];
    const float* WQ = (const float*)d_in[1];
    const float* WK = (const float*)d_in[2];
    const float* WV = (const float*)d_in[3];
    const float* gw = (const float*)d_in[4];
    const float* gb = (const float*)d_in[5];
    float* out = (float*)d_out;

    float *pQ, *pK, *pV, *pO, *pA;
    cudaGetSymbolAddress((void**)&pQ, g_Q);
    cudaGetSymbolAddress((void**)&pK, g_K);
    cudaGetSymbolAddress((void**)&pV, g_V);
    cudaGetSymbolAddress((void**)&pO, g_O);
    cudaGetSymbolAddress((void**)&pA, g_A);

    init_decay_kernel<<<(SEQ + 255) / 256, 256>>>();

    // Projections: (B*T, 1024) @ (1024, 1024)
    dim3 gProj(DMODEL / 128, (BATCH * SEQ) / 128, 1);
    tf32gemm<false, false><<<gProj, 256>>>(X, WQ, pQ, DMODEL, DMODEL, DMODEL, DMODEL, 0, 0, 0);
    tf32gemm<false, false><<<gProj, 256>>>(X, WK, pK, DMODEL, DMODEL, DMODEL, DMODEL, 0, 0, 0);
    tf32gemm<false, false><<<gProj, 256>>>(X, WV, pV, DMODEL, DMODEL, DMODEL, DMODEL, 0, 0, 0);

    // rope + silu (Q, K), silu (V)
    int pairs = BATCH * SEQ * (DMODEL / 2);
    int ablocks = (pairs + 255) / 256;
    act_kernel<true ><<<ablocks, 256>>>(pQ);
    act_kernel<true ><<<ablocks, 256>>>(pK);
    act_kernel<false><<<ablocks, 256>>>(pV);

    // A = Q K^T with decay epilogue (per batch)
    dim3 gA(SEQ / 128, SEQ / 128, BATCH);
    tf32gemm<true, true><<<gA, 256>>>(pQ, pK, pA, DMODEL, DMODEL, DMODEL, SEQ,
                                      (size_t)SEQ * DMODEL, (size_t)SEQ * DMODEL,
                                      (size_t)SEQ * SEQ);

    // O = A V (per batch)
    dim3 gO(DMODEL / 128, SEQ / 128, BATCH);
    tf32gemm<false, false><<<gO, 256>>>(pA, pV, pO, SEQ, SEQ, DMODEL, DMODEL,
                                        (size_t)SEQ * SEQ, (size_t)SEQ * DMODEL,
                                        (size_t)SEQ * DMODEL);

    // GroupNorm -> d_out
    groupnorm_kernel<<<BATCH * SEQ, 256>>>(pO, gw, gb, out);
}